// round 4
// baseline (speedup 1.0000x reference)
#include <cuda_runtime.h>
#include <cuda_fp16.h>
#include <cstdint>

// ============================================================================
// CATSCluster fused kernel — sm_103 baseline-PTX tensor path, 2 CTAs/SM.
//
//   X = X_data[:, 1:, :]  (16 x 4096 x 2304 fp32)
//   p1 = X[.., 768:1536] -> relu(relu(p1@W1^T)@W2^T) = Ha2   (128)
//   p2 = X[..,1536:2304] -> same weights             = Hb2
//   q  = X[..,   0: 768] -> relu(relu(q @W3^T)@W4^T) = Hq2
//   out = tanh(relu( (Hq2 * |Ha2-Hb2|) @ W5^T ))
//
// Round-4 vs round-3 (369us):
//  * Block = 64 rows / 256 threads, smem 96.25KB -> 2 CTAs per SM (16 warps).
//    Independent barrier domains cover each other's convert/epilogue bubbles.
//  * Warp tiles: L1 32m x 64n (64 accum regs), L2 16m x 64n.
//  * No explicit B prefetch regs (16 warps hide L2 latency); launch_bounds
//    caps at 128 regs to guarantee 2-CTA residency (r3 was at 255, spilling).
// ============================================================================

// ---- smem layout (bytes), 64-row block ----
static constexpr int A32_STRIDE = 272;                  // 64 f32 + 16B pad
static constexpr int A32_BYTES  = 64 * A32_STRIDE;      // 17408
static constexpr int SM_W5   = 0;                       // 512 B
static constexpr int SM_PART = 512;                     // float[64][2]
static constexpr int SM_A32  = 1024;                    // 2 x 17408
static constexpr int SM_AF16 = SM_A32 + 2 * A32_BYTES;  // 64 x 144 = 9216
static constexpr int SM_H1   = SM_AF16 + 64 * 144;      // 64 x 528 = 33792
static constexpr int SM_D    = SM_H1 + 64 * 528;        // 64 x 272 = 17408
static constexpr int SMEM_BYTES = SM_D + 64 * 272;      // 96256

// Fragment-packed fp16 weights (prep kernel fills these every launch).
// L1: [chunk 12][n8-tile 32][k16 4][lane 32][4 halves]
// L2: [n8-tile 16][k16 16][lane 32][4 halves]
__device__ __half g_B1[2][12 * 32 * 4 * 32 * 4];   // W1, W3
__device__ __half g_B2[2][16 * 16 * 32 * 4];       // W2, W4

// ---------------------------------------------------------------- helpers
__device__ __forceinline__ uint32_t smem_u32(const void* p) {
    return (uint32_t)__cvta_generic_to_shared(p);
}
__device__ __forceinline__ void ldm_x4(uint32_t r[4], uint32_t addr) {
    asm volatile("ldmatrix.sync.aligned.m8n8.x4.shared.b16 {%0,%1,%2,%3}, [%4];"
                 : "=r"(r[0]), "=r"(r[1]), "=r"(r[2]), "=r"(r[3]) : "r"(addr));
}
__device__ __forceinline__ void mma16816(float c[4], const uint32_t a[4],
                                         uint32_t b0, uint32_t b1) {
    asm volatile(
        "mma.sync.aligned.m16n8k16.row.col.f32.f16.f16.f32 "
        "{%0,%1,%2,%3}, {%4,%5,%6,%7}, {%8,%9}, {%0,%1,%2,%3};"
        : "+f"(c[0]), "+f"(c[1]), "+f"(c[2]), "+f"(c[3])
        : "r"(a[0]), "r"(a[1]), "r"(a[2]), "r"(a[3]), "r"(b0), "r"(b1));
}
__device__ __forceinline__ void cp_async16(uint32_t saddr, const void* gaddr) {
    asm volatile("cp.async.cg.shared.global [%0], [%1], 16;"
                 :: "r"(saddr), "l"(gaddr) : "memory");
}
__device__ __forceinline__ void cp_commit() {
    asm volatile("cp.async.commit_group;" ::: "memory");
}
__device__ __forceinline__ void cp_wait1() {
    asm volatile("cp.async.wait_group 1;" ::: "memory");
}
__device__ __forceinline__ void cp_wait0() {
    asm volatile("cp.async.wait_group 0;" ::: "memory");
}
__device__ __forceinline__ uint32_t h2u(__half2 h) {
    return *reinterpret_cast<uint32_t*>(&h);
}

// ------------------------------------------------- weight frag-pack kernel
__global__ void prep_kernel(const float* __restrict__ W1, const float* __restrict__ W2,
                            const float* __restrict__ W3, const float* __restrict__ W4) {
    int e = blockIdx.x * blockDim.x + threadIdx.x;    // 0 .. 196607
    {
        // L1 weights: W[n(256)][k(768)]
        int n = e / 768, k = e % 768;
        int kc = k >> 6;
        int j  = (k >> 4) & 3;
        int kl = k & 15;
        int p  = kl >> 3;
        int pos = kl & 7;
        int lane = (n & 7) * 4 + (pos >> 1);
        int h = pos & 1;
        int idx = ((((kc * 32 + (n >> 3)) * 4 + j) * 32 + lane) << 2) + p * 2 + h;
        g_B1[0][idx] = __float2half_rn(W1[e]);
        g_B1[1][idx] = __float2half_rn(W3[e]);
    }
    if (e < 128 * 256) {
        // L2 weights: W[n(128)][k(256)]
        int n = e / 256, k = e % 256;
        int j  = k >> 4;
        int kl = k & 15;
        int p  = kl >> 3;
        int pos = kl & 7;
        int lane = (n & 7) * 4 + (pos >> 1);
        int h = pos & 1;
        int idx = ((((n >> 3) * 16 + j) * 32 + lane) << 2) + p * 2 + h;
        g_B2[0][idx] = __float2half_rn(W2[e]);
        g_B2[1][idx] = __float2half_rn(W4[e]);
    }
}

// ----------------------------------------------------------------- main kernel
__global__ void __launch_bounds__(256, 2) fused_kernel(
    const float* __restrict__ X, const float* __restrict__ W5, float* __restrict__ out) {
    extern __shared__ __align__(128) char smem[];
    const uint32_t sb = smem_u32(smem);
    const int tid = threadIdx.x;
    const int w   = tid >> 5;
    const int l   = tid & 31;
    const int lq  = l & 3;

    const long long blk = blockIdx.x;                  // 1024 blocks, 64 rows each
    const float* Xbase = X + ((blk >> 6) * 4097LL + (blk & 63) * 64LL + 1LL) * 2304LL;

    // chunk c (0..35): slice s=c/12, k-chunk kc=c%12, A32 buffer c&1.
    // slice col offsets: s0->p1(+768), s1->p2(+1536), s2->q(+0)
    auto issue_chunk = [&](int c) {
        int ss = c / 12, kk = c % 12;
        int soff = (ss == 0) ? 768 : (ss == 1) ? 1536 : 0;
        const int row = tid >> 2, seg = tid & 3;       // 4 threads/row, 64B each
        const float* src = Xbase + (long long)row * 2304 + soff + kk * 64 + seg * 16;
        uint32_t dst = sb + SM_A32 + (c & 1) * A32_BYTES + row * A32_STRIDE + seg * 64;
        #pragma unroll
        for (int i = 0; i < 4; i++)
            cp_async16(dst + i * 16, src + i * 4);
        cp_commit();
    };

    issue_chunk(0);
    if (tid < 128) ((float*)(smem + SM_W5))[tid] = W5[tid];

    // L1 warp tile: 32m x 64n  (warp grid 2m x 4n).
    const int wm = w >> 2, wq = w & 3;
    // L2 warp tile: 16m x 64n  (warp grid 4m x 2n).
    const int wm2 = w >> 1, wn2 = w & 1;

    const float* W5s = (const float*)(smem + SM_W5);
    float* parts = (float*)(smem + SM_PART);

    int c = 0;
    for (int s = 0; s < 3; s++) {
        const uint2* B1g = (const uint2*)g_B1[s == 2 ? 1 : 0];
        const uint2* B2g = (const uint2*)g_B2[s == 2 ? 1 : 0];

        // ================= layer 1: acc[2 mf][8 t][4] = Xslice @ W^T ============
        float acc[2][8][4];
        #pragma unroll
        for (int a = 0; a < 2; a++)
            #pragma unroll
            for (int b = 0; b < 8; b++)
                #pragma unroll
                for (int q = 0; q < 4; q++) acc[a][b][q] = 0.f;

        for (int kc = 0; kc < 12; kc++) {
            if (c + 1 < 36) { issue_chunk(c + 1); cp_wait1(); }
            else            { cp_wait0(); }
            __syncthreads();          // chunk c arrived; prev compute done

            // ---- convert fp32 chunk -> fp16 AF16 (pad-144B rows) ----
            {
                const int r = tid >> 2, seg = tid & 3;   // 64B f32 -> 32B f16 each
                const float4* src = (const float4*)(smem + SM_A32 + (c & 1) * A32_BYTES
                                                    + r * A32_STRIDE + seg * 64);
                uint32_t dst = sb + SM_AF16 + r * 144 + seg * 32;
                #pragma unroll
                for (int i = 0; i < 4; i++) {
                    float4 v = src[i];
                    uint32_t p0 = h2u(__floats2half2_rn(v.x, v.y));
                    uint32_t p1 = h2u(__floats2half2_rn(v.z, v.w));
                    asm volatile("st.shared.v2.b32 [%0], {%1,%2};"
                                 :: "r"(dst + i * 8), "r"(p0), "r"(p1));
                }
            }
            __syncthreads();

            // ---- compute: 4 k16 steps; B frags from global (L2) ----
            const uint32_t aBase = sb + SM_AF16 + (wm * 32 + (l & 15)) * 144 + (l >> 4) * 16;
            const uint2* bG = B1g + kc * 4096 + wq * 1024 + l;
            #pragma unroll
            for (int j = 0; j < 4; j++) {
                uint2 bv[8];
                #pragma unroll
                for (int t = 0; t < 8; t++) bv[t] = bG[(t * 4 + j) * 32];
                uint32_t afr[2][4];
                #pragma unroll
                for (int mf = 0; mf < 2; mf++)
                    ldm_x4(afr[mf], aBase + mf * 16 * 144 + j * 32);
                #pragma unroll
                for (int mf = 0; mf < 2; mf++)
                    #pragma unroll
                    for (int t = 0; t < 8; t++)
                        mma16816(acc[mf][t], afr[mf], bv[t].x, bv[t].y);
            }
            c++;
        }
        // (next slice's chunk 0 already in flight -> overlaps epilogue below)

        // ================= relu -> fp16 -> H1 smem (pad-528B rows) ==============
        #pragma unroll
        for (int mf = 0; mf < 2; mf++) {
            #pragma unroll
            for (int t = 0; t < 8; t++) {
                const int r0 = wm * 32 + mf * 16 + (l >> 2);
                const int col = wq * 64 + t * 8 + lq * 2;
                float* cc = acc[mf][t];
                *(uint32_t*)(smem + SM_H1 + r0 * 528 + col * 2) =
                    h2u(__floats2half2_rn(fmaxf(cc[0], 0.f), fmaxf(cc[1], 0.f)));
                *(uint32_t*)(smem + SM_H1 + (r0 + 8) * 528 + col * 2) =
                    h2u(__floats2half2_rn(fmaxf(cc[2], 0.f), fmaxf(cc[3], 0.f)));
            }
        }
        __syncthreads();

        // ================= layer 2: acc2[8 t][4] = H1 @ W2^T ====================
        float acc2[8][4];
        #pragma unroll
        for (int b = 0; b < 8; b++)
            #pragma unroll
            for (int q = 0; q < 4; q++) acc2[b][q] = 0.f;

        {
            const uint32_t aBase = sb + SM_H1 + (wm2 * 16 + (l & 15)) * 528 + (l >> 4) * 16;
            const uint2* bG = B2g + wn2 * 4096 + l;
            #pragma unroll
            for (int j = 0; j < 16; j++) {
                uint2 bv[8];
                #pragma unroll
                for (int t = 0; t < 8; t++) bv[t] = bG[t * 512 + j * 32];
                uint32_t afr[4];
                ldm_x4(afr, aBase + j * 32);
                #pragma unroll
                for (int t = 0; t < 8; t++)
                    mma16816(acc2[t], afr, bv[t].x, bv[t].y);
            }
        }
        __syncthreads();   // H1 reads done before anything reuses it

        // ================= combine via D buffer (pad-272B rows, warp-private) ===
        if (s == 0) {
            #pragma unroll
            for (int t = 0; t < 8; t++) {
                const int r0 = wm2 * 16 + (l >> 2);
                const int col = wn2 * 64 + t * 8 + lq * 2;
                float* cc = acc2[t];
                *(uint32_t*)(smem + SM_D + r0 * 272 + col * 2) =
                    h2u(__floats2half2_rn(fmaxf(cc[0], 0.f), fmaxf(cc[1], 0.f)));
                *(uint32_t*)(smem + SM_D + (r0 + 8) * 272 + col * 2) =
                    h2u(__floats2half2_rn(fmaxf(cc[2], 0.f), fmaxf(cc[3], 0.f)));
            }
        } else if (s == 1) {
            #pragma unroll
            for (int t = 0; t < 8; t++) {
                const int r0 = wm2 * 16 + (l >> 2);
                const int col = wn2 * 64 + t * 8 + lq * 2;
                float* cc = acc2[t];
                uint32_t* d0 = (uint32_t*)(smem + SM_D + r0 * 272 + col * 2);
                uint32_t* d1 = (uint32_t*)(smem + SM_D + (r0 + 8) * 272 + col * 2);
                float2 fa = __half22float2(*(__half2*)d0);
                float2 fb = __half22float2(*(__half2*)d1);
                *d0 = h2u(__floats2half2_rn(fabsf(fa.x - fmaxf(cc[0], 0.f)),
                                            fabsf(fa.y - fmaxf(cc[1], 0.f))));
                *d1 = h2u(__floats2half2_rn(fabsf(fb.x - fmaxf(cc[2], 0.f)),
                                            fabsf(fb.y - fmaxf(cc[3], 0.f))));
            }
        } else {
            float pd[2] = {0.f, 0.f};
            #pragma unroll
            for (int t = 0; t < 8; t++) {
                const int r0 = wm2 * 16 + (l >> 2);
                const int col = wn2 * 64 + t * 8 + lq * 2;
                float* cc = acc2[t];
                float2 da = __half22float2(*(__half2*)(smem + SM_D + r0 * 272 + col * 2));
                float2 db = __half22float2(*(__half2*)(smem + SM_D + (r0 + 8) * 272 + col * 2));
                float w0 = W5s[col], w1 = W5s[col + 1];
                pd[0] += w0 * fmaxf(cc[0], 0.f) * da.x + w1 * fmaxf(cc[1], 0.f) * da.y;
                pd[1] += w0 * fmaxf(cc[2], 0.f) * db.x + w1 * fmaxf(cc[3], 0.f) * db.y;
            }
            #pragma unroll
            for (int rr = 0; rr < 2; rr++) {
                float v = pd[rr];
                v += __shfl_xor_sync(0xFFFFFFFF, v, 1);
                v += __shfl_xor_sync(0xFFFFFFFF, v, 2);
                if (lq == 0) {
                    int row = wm2 * 16 + rr * 8 + (l >> 2);
                    parts[row * 2 + wn2] = v;
                }
            }
        }
    }

    __syncthreads();
    if (tid < 64) {
        float sum = parts[tid * 2] + parts[tid * 2 + 1];
        out[blk * 64 + tid] = tanhf(fmaxf(sum, 0.f));
    }
}

// ------------------------------------------------------------------- launcher
extern "C" void kernel_launch(void* const* d_in, const int* in_sizes, int n_in,
                              void* d_out, int out_size) {
    const float* X  = (const float*)d_in[0];
    const float* W1 = (const float*)d_in[1];
    const float* W2 = (const float*)d_in[2];
    const float* W3 = (const float*)d_in[3];
    const float* W4 = (const float*)d_in[4];
    const float* W5 = (const float*)d_in[5];
    (void)in_sizes; (void)n_in; (void)out_size;

    cudaFuncSetAttribute(fused_kernel, cudaFuncAttributeMaxDynamicSharedMemorySize, SMEM_BYTES);

    prep_kernel<<<768, 256>>>(W1, W2, W3, W4);
    fused_kernel<<<1024, 256, SMEM_BYTES>>>(X, W5, (float*)d_out);
}